// round 7
// baseline (speedup 1.0000x reference)
#include <cuda_runtime.h>

// Fixed problem shape
#define BATCH 8
#define CDIM  64
#define NPTS  4096
#define KNN   20
#define TM    128    // targets per block == threads per block
#define TC    32     // candidate tile size
#define NSPLIT 4
#define QN (NPTS / NSPLIT)   // candidates per partial = 1024

// Split-K partial results: [part][k][b*NPTS+n], coalesced in n. (~21 MB static)
__device__ unsigned long long g_part[NSPLIT][KNN][BATCH * NPTS];

// Packed helpers: two independent rn-rounded fp32 FMAs per instruction.
__device__ __forceinline__ void fma2(unsigned long long& acc,
                                     unsigned long long a2,
                                     unsigned long long b2) {
    asm("fma.rn.f32x2 %0, %1, %2, %0;" : "+l"(acc) : "l"(a2), "l"(b2));
}
__device__ __forceinline__ unsigned long long dup2(float a) {
    unsigned long long r;
    asm("mov.b64 %0, {%1, %1};" : "=l"(r) : "f"(a));
    return r;
}
__device__ __forceinline__ void unpack2(unsigned long long v, float& lo, float& hi) {
    asm("mov.b64 {%0, %1}, %2;" : "=f"(lo), "=f"(hi) : "l"(v));
}

// ---------------------------------------------------------------------------
// Kernel 1: each CTA = 128 targets x one candidate quarter (1024 candidates).
// Per-lane distance arithmetic bit-identical to passing rounds 3-6:
//   sequential ascending-c FMA dot & csq; d2 = fma(dot, -2, sqt + csq).
// (fma.rn.f32x2 = two independent scalar rn FMAs -> same bits per lane.)
// Top-K: packed u64 keys (d2_bits<<32 | idx) == exact lax.top_k order;
// immediate insertion-sort into SMEM-resident sorted top-20 per thread.
// ---------------------------------------------------------------------------
__global__ void __launch_bounds__(TM) knn_part(const float* __restrict__ x) {
    __shared__ __align__(16) float sf[CDIM * TC];       // 8 KB tile
    __shared__ __align__(16) float s_csq[TC];
    __shared__ unsigned long long s_top[KNN][TM];       // 20 KB sorted top-K

    const int b    = blockIdx.y;
    const int part = blockIdx.z;
    const int tid  = threadIdx.x;
    const int tgt  = blockIdx.x * TM + tid;
    const float* xb = x + b * CDIM * NPTS;

    // Target features -> registers; target squared norm (ascending c).
    float tq[CDIM];
    float sqt = 0.f;
#pragma unroll
    for (int c = 0; c < CDIM; c++) {
        tq[c] = xb[c * NPTS + tgt];
        sqt = fmaf(tq[c], tq[c], sqt);
    }

#pragma unroll
    for (int k = 0; k < KNN; k++) s_top[k][tid] = ~0ull;
    unsigned long long thresh = ~0ull;   // == s_top[19][tid]

    const int cand = tid & (TC - 1);
    const int cgrp = tid >> 5;           // 0..3 (TM = 4*TC)
    const int jbeg = part * QN;

    for (int jt = 0; jt < QN; jt += TC) {
        const int j0 = jbeg + jt;
        __syncthreads();
#pragma unroll
        for (int c = cgrp; c < CDIM; c += 4)
            sf[c * TC + cand] = xb[c * NPTS + j0 + cand];
        __syncthreads();
        if (tid < TC) {                  // csq: ascending c, unchanged order
            float s = 0.f;
#pragma unroll
            for (int c = 0; c < CDIM; c++) {
                float v = sf[c * TC + tid];
                s = fmaf(v, v, s);
            }
            s_csq[tid] = s;
        }
        __syncthreads();

        for (int jg = 0; jg < TC; jg += 8) {
            unsigned long long a01 = 0, a23 = 0, a45 = 0, a67 = 0;
#pragma unroll
            for (int c = 0; c < CDIM; c++) {
                const ulonglong2* rp =
                    reinterpret_cast<const ulonglong2*>(sf + c * TC + jg);
                ulonglong2 v0 = rp[0];          // cands jg..jg+3 (2 pairs)
                ulonglong2 v1 = rp[1];          // cands jg+4..jg+7
                unsigned long long a2 = dup2(tq[c]);
                fma2(a01, a2, v0.x);
                fma2(a23, a2, v0.y);
                fma2(a45, a2, v1.x);
                fma2(a67, a2, v1.y);
            }
            float dots[8];
            unpack2(a01, dots[0], dots[1]);
            unpack2(a23, dots[2], dots[3]);
            unpack2(a45, dots[4], dots[5]);
            unpack2(a67, dots[6], dots[7]);

            float4 cs0 = *reinterpret_cast<const float4*>(s_csq + jg);
            float4 cs1 = *reinterpret_cast<const float4*>(s_csq + jg + 4);
            float csv[8] = {cs0.x, cs0.y, cs0.z, cs0.w,
                            cs1.x, cs1.y, cs1.z, cs1.w};
#pragma unroll
            for (int u = 0; u < 8; u++) {
                int   j = j0 + jg + u;
                float t = sqt + csv[u];
                float d = fmaf(dots[u], -2.0f, t);   // one final rounding
                unsigned long long key =
                    ((unsigned long long)__float_as_uint(d) << 32) |
                    (unsigned int)j;
                if (j != tgt && key < thresh) {
                    int k = KNN - 1;                 // insert, drop old 20th
                    while (k > 0 && s_top[k - 1][tid] > key) {
                        s_top[k][tid] = s_top[k - 1][tid];
                        k--;
                    }
                    s_top[k][tid] = key;
                    thresh = s_top[KNN - 1][tid];
                }
            }
        }
    }

    // Write sorted partial top-20 (coalesced in target index).
    const int col = b * NPTS + tgt;
#pragma unroll
    for (int p = 0; p < KNN; p++)
        g_part[part][p][col] = s_top[p][tid];
}

// ---------------------------------------------------------------------------
// Kernel 2: exact 4-way tournament merge of four sorted top-20 key lists.
// Keys are globally unique (index embedded), so u64 order is total & exact.
// ---------------------------------------------------------------------------
__global__ void __launch_bounds__(64) knn_merge(float* __restrict__ out) {
    __shared__ unsigned long long sm[NSPLIT][KNN][64];  // 40 KB
    const int t   = threadIdx.x;
    const int idx = blockIdx.x * 64 + t;                // 0 .. B*N-1
#pragma unroll
    for (int p = 0; p < KNN; p++)
#pragma unroll
        for (int l = 0; l < NSPLIT; l++)
            sm[l][p][t] = g_part[l][p][idx];            // coalesced

    const int b = idx >> 12;                            // NPTS = 4096
    const int n = idx & (NPTS - 1);
    const int base0 = ((0 * BATCH + b) * NPTS + n) * KNN;
    const int base1 = ((1 * BATCH + b) * NPTS + n) * KNN;
    const float ftgt = (float)n;

    int i0 = 0, i1 = 0, i2 = 0, i3 = 0;
#pragma unroll
    for (int p = 0; p < KNN; p++) {
        unsigned long long v0 = sm[0][i0][t];
        unsigned long long v1 = sm[1][i1][t];
        unsigned long long v2 = sm[2][i2][t];
        unsigned long long v3 = sm[3][i3][t];
        bool l01 = v0 <= v1; unsigned long long m01 = l01 ? v0 : v1;
        bool l23 = v2 <= v3; unsigned long long m23 = l23 ? v2 : v3;
        bool lf  = m01 <= m23;
        unsigned long long m = lf ? m01 : m23;
        i0 += ( lf &&  l01) ? 1 : 0;
        i1 += ( lf && !l01) ? 1 : 0;
        i2 += (!lf &&  l23) ? 1 : 0;
        i3 += (!lf && !l23) ? 1 : 0;
        out[base0 + p] = (float)(int)(unsigned int)(m & 0xffffffffu);
        out[base1 + p] = ftgt;
    }
}

// ---------------------------------------------------------------------------
extern "C" void kernel_launch(void* const* d_in, const int* in_sizes, int n_in,
                              void* d_out, int out_size) {
    (void)in_sizes; (void)n_in; (void)out_size;
    const float* x = (const float*)d_in[0];
    float* out = (float*)d_out;

    dim3 grid(NPTS / TM, BATCH, NSPLIT);    // 32 x 8 x 4 = 1024 CTAs
    knn_part<<<grid, TM>>>(x);
    knn_merge<<<(BATCH * NPTS) / 64, 64>>>(out);
}

// round 8
// speedup vs baseline: 2.3880x; 2.3880x over previous
#include <cuda_runtime.h>

// Fixed problem shape
#define BATCH 8
#define CDIM  64
#define NPTS  4096
#define KNN   20
#define TM    128    // targets per block == threads per block
#define TC    32     // candidate tile size
#define CAP   16     // per-thread candidate buffer slots
#define NSPLIT 2
#define HALF_N (NPTS / NSPLIT)

// Scratch for split-K partial results: [half][k][b*NPTS+n], coalesced in n.
__device__ unsigned long long g_part[NSPLIT][KNN][BATCH * NPTS];

// Packed helpers: fma.rn.f32x2 = two independent rn-rounded fp32 FMAs.
__device__ __forceinline__ void fma2(unsigned long long& acc,
                                     unsigned long long a2,
                                     unsigned long long b2) {
    asm("fma.rn.f32x2 %0, %1, %2, %0;" : "+l"(acc) : "l"(a2), "l"(b2));
}
__device__ __forceinline__ unsigned long long dup2(float a) {
    unsigned long long r;
    asm("mov.b64 %0, {%1, %1};" : "=l"(r) : "f"(a));
    return r;
}
__device__ __forceinline__ void unpack2(unsigned long long v, float& lo, float& hi) {
    asm("mov.b64 {%0, %1}, %2;" : "=f"(lo), "=f"(hi) : "l"(v));
}

// ---------------------------------------------------------------------------
// Kernel 1 (structure identical to the 804us round-6 winner; ONLY the inner
// product loop changed to packed f32x2, 8 candidates/group).
// Per-lane distance arithmetic bit-identical to all passing rounds:
//   sequential ascending-c FMA dot & csq; d2 = fma(dot, -2, sqt + csq).
// Top-K: threshold + deferred buffer merge on packed u64 keys
// (d2_bits<<32 | idx) == exact lax.top_k (dist asc, lower idx first).
// ---------------------------------------------------------------------------
__global__ void __launch_bounds__(TM) knn_half(const float* __restrict__ x) {
    __shared__ __align__(16) float sf[CDIM * TC];           // 8 KB tile
    __shared__ __align__(16) float s_csq[TC];
    __shared__ unsigned long long s_top[KNN][TM];           // 20 KB sorted topK
    __shared__ unsigned long long s_buf[CAP][TM];           // 16 KB buffers

    const int b    = blockIdx.y;
    const int half = blockIdx.z;
    const int tid  = threadIdx.x;
    const int tgt  = blockIdx.x * TM + tid;
    const float* xb = x + b * CDIM * NPTS;

    // Target features -> registers; target squared norm (ascending c).
    float tq[CDIM];
    float sqt = 0.f;
#pragma unroll
    for (int c = 0; c < CDIM; c++) {
        tq[c] = xb[c * NPTS + tgt];
        sqt = fmaf(tq[c], tq[c], sqt);
    }

#pragma unroll
    for (int k = 0; k < KNN; k++) s_top[k][tid] = ~0ull;
    unsigned long long thresh = ~0ull;
    int cnt = 0;

    const int cand = tid & (TC - 1);
    const int cgrp = tid >> 5;          // 0..3 (TM = 4*TC)
    const int jbeg = half * HALF_N;

    for (int jt = 0; jt < HALF_N; jt += TC) {
        const int j0 = jbeg + jt;
        __syncthreads();
#pragma unroll
        for (int c = cgrp; c < CDIM; c += 4)
            sf[c * TC + cand] = xb[c * NPTS + j0 + cand];
        __syncthreads();
        if (tid < TC) {                 // csq: ascending c, unchanged order
            float s = 0.f;
#pragma unroll
            for (int c = 0; c < CDIM; c++) {
                float v = sf[c * TC + tid];
                s = fmaf(v, v, s);
            }
            s_csq[tid] = s;
        }
        __syncthreads();

        for (int jg = 0; jg < TC; jg += 8) {
            unsigned long long a01 = 0, a23 = 0, a45 = 0, a67 = 0;
#pragma unroll
            for (int c = 0; c < CDIM; c++) {
                const ulonglong2* rp =
                    reinterpret_cast<const ulonglong2*>(sf + c * TC + jg);
                ulonglong2 v0 = rp[0];          // cands jg..jg+3
                ulonglong2 v1 = rp[1];          // cands jg+4..jg+7
                unsigned long long a2 = dup2(tq[c]);
                fma2(a01, a2, v0.x);
                fma2(a23, a2, v0.y);
                fma2(a45, a2, v1.x);
                fma2(a67, a2, v1.y);
            }
            float dots[8];
            unpack2(a01, dots[0], dots[1]);
            unpack2(a23, dots[2], dots[3]);
            unpack2(a45, dots[4], dots[5]);
            unpack2(a67, dots[6], dots[7]);

            float4 cs0 = *reinterpret_cast<const float4*>(s_csq + jg);
            float4 cs1 = *reinterpret_cast<const float4*>(s_csq + jg + 4);
            float csv[8] = {cs0.x, cs0.y, cs0.z, cs0.w,
                            cs1.x, cs1.y, cs1.z, cs1.w};
#pragma unroll
            for (int u = 0; u < 8; u++) {
                int   j = j0 + jg + u;
                float t = sqt + csv[u];
                float d = fmaf(dots[u], -2.0f, t);   // one final rounding
                unsigned long long key =
                    ((unsigned long long)__float_as_uint(d) << 32) |
                    (unsigned int)j;
                if (j != tgt && key < thresh) {      // cheap append path
                    s_buf[cnt][tid] = key;
                    cnt++;
                }
            }
            // Deferred warp-wide merge; margin 8 so next group can't overflow.
            if (__any_sync(0xffffffffu, cnt > CAP - 8)) {
                for (int i = 0; i < cnt; i++) {
                    unsigned long long kv = s_buf[i][tid];
                    if (kv < s_top[KNN - 1][tid]) {
                        int k = KNN - 1;
                        while (k > 0 && s_top[k - 1][tid] > kv) {
                            s_top[k][tid] = s_top[k - 1][tid];
                            k--;
                        }
                        s_top[k][tid] = kv;
                    }
                }
                cnt = 0;
                thresh = s_top[KNN - 1][tid];
            }
        }
    }

    for (int i = 0; i < cnt; i++) {          // leftovers
        unsigned long long kv = s_buf[i][tid];
        if (kv < s_top[KNN - 1][tid]) {
            int k = KNN - 1;
            while (k > 0 && s_top[k - 1][tid] > kv) {
                s_top[k][tid] = s_top[k - 1][tid];
                k--;
            }
            s_top[k][tid] = kv;
        }
    }

    // Write sorted partial top-20 (coalesced in target index).
    const int col = b * NPTS + tgt;
#pragma unroll
    for (int p = 0; p < KNN; p++)
        g_part[half][p][col] = s_top[p][tid];
}

// ---------------------------------------------------------------------------
// Kernel 2: exact 2-pointer merge of the two sorted per-half top-20 lists.
// ---------------------------------------------------------------------------
__global__ void __launch_bounds__(128) knn_merge(float* __restrict__ out) {
    __shared__ unsigned long long sa[KNN][128];
    __shared__ unsigned long long sb[KNN][128];
    const int t   = threadIdx.x;
    const int idx = blockIdx.x * 128 + t;      // 0 .. B*N-1
#pragma unroll
    for (int p = 0; p < KNN; p++) {
        sa[p][t] = g_part[0][p][idx];          // coalesced
        sb[p][t] = g_part[1][p][idx];
    }
    const int b = idx >> 12;                   // NPTS = 4096
    const int n = idx & (NPTS - 1);
    const int base0 = ((0 * BATCH + b) * NPTS + n) * KNN;
    const int base1 = ((1 * BATCH + b) * NPTS + n) * KNN;
    const float ftgt = (float)n;

    int ia = 0, ib = 0;
#pragma unroll
    for (int p = 0; p < KNN; p++) {
        unsigned long long va = sa[ia][t];
        unsigned long long vb = sb[ib][t];
        bool ta = va < vb;                     // u64 order == exact key order
        unsigned long long v = ta ? va : vb;
        ia += ta ? 1 : 0;
        ib += ta ? 0 : 1;
        out[base0 + p] = (float)(int)(unsigned int)(v & 0xffffffffu);
        out[base1 + p] = ftgt;
    }
}

// ---------------------------------------------------------------------------
extern "C" void kernel_launch(void* const* d_in, const int* in_sizes, int n_in,
                              void* d_out, int out_size) {
    (void)in_sizes; (void)n_in; (void)out_size;
    const float* x = (const float*)d_in[0];
    float* out = (float*)d_out;

    dim3 grid(NPTS / TM, BATCH, NSPLIT);       // 32 x 8 x 2 = 512 CTAs
    knn_half<<<grid, TM>>>(x);
    knn_merge<<<(BATCH * NPTS) / 128, 128>>>(out);
}